// round 7
// baseline (speedup 1.0000x reference)
#include <cuda_runtime.h>
#include <cuda_bf16.h>
#include <mma.h>
#include <math.h>
#include <stdint.h>

using namespace nvcuda;

#define NN 50000
#define NPAD 50048            // 391 * 128
#define EE 800000
#define INF_ 256
#define HH 4
#define FF 64
#define NH (NN*HH)            // 200000
#define EH (EE*HH)            // 3200000
#define SLOPE 0.2f
#define LCLIP (-23.0258509f)  // log(1e-10)

// ---------------- scratch (static device globals; no allocation) ------------
__device__ float g_h [NPAD*HH*FF];   // padded rows for guard-free wmma stores
__device__ float g_x1[NN*HH*FF];
__device__ float g_x2[NN*HH*FF];
__device__ float g_x3[NN*HH*FF];
__device__ float g_el[NH], g_er[NH], g_al[NH];
__device__ float g_sum_src[NH], g_sum_dst[NH];   // exp-sums, then logs in-place
__device__ float g_e[EH];      // leaky_relu(el[src]+er[dst])
__device__ float g_c[EE*HH];   // per-edge coefficient, CSR order: [pos][hd]
__device__ int   g_indeg[NN], g_outdeg[NN], g_cnt[NN];
__device__ int   g_off[NN+1];
__device__ int   g_csr_src[EE];
__device__ float g_nin[NN], g_nout[NN];
__device__ int   g_bsum[256], g_boff[256];
__device__ __nv_bfloat16 g_Wh[256*256];   // [k][n] row-major, split hi/lo
__device__ __nv_bfloat16 g_Wl[256*256];

// ---------------- helpers ---------------------------------------------------
__device__ __forceinline__ float leaky(float x) { return x > 0.f ? x : SLOPE * x; }

__device__ __forceinline__ float warpAllReduce(float v) {
#pragma unroll
    for (int o = 16; o; o >>= 1) v += __shfl_xor_sync(0xffffffffu, v, o);
    return v;
}

// ---------------- kernels ---------------------------------------------------
__global__ void init_kernel() {
    int i = blockIdx.x * blockDim.x + threadIdx.x;
    if (i < NN) { g_indeg[i] = 0; g_outdeg[i] = 0; g_cnt[i] = 0; }
    if (i < NH) { g_sum_src[i] = 0.f; g_sum_dst[i] = 0.f; }
}

// W -> split bf16 hi/lo, same [k][n] layout
__global__ void convertW_kernel(const float* __restrict__ W) {
    int idx = blockIdx.x * 256 + threadIdx.x;      // 65536/4 threads
    if (idx >= 64 * 256) return;
    float4 v = ((const float4*)W)[idx];
    __nv_bfloat16 hx = __float2bfloat16_rn(v.x), hy = __float2bfloat16_rn(v.y);
    __nv_bfloat16 hz = __float2bfloat16_rn(v.z), hw = __float2bfloat16_rn(v.w);
    ((__nv_bfloat162*)g_Wh)[idx * 2]     = __nv_bfloat162(hx, hy);
    ((__nv_bfloat162*)g_Wh)[idx * 2 + 1] = __nv_bfloat162(hz, hw);
    ((__nv_bfloat162*)g_Wl)[idx * 2]     = __nv_bfloat162(
        __float2bfloat16_rn(v.x - __bfloat162float(hx)),
        __float2bfloat16_rn(v.y - __bfloat162float(hy)));
    ((__nv_bfloat162*)g_Wl)[idx * 2 + 1] = __nv_bfloat162(
        __float2bfloat16_rn(v.z - __bfloat162float(hz)),
        __float2bfloat16_rn(v.w - __bfloat162float(hw)));
}

// tensor-core GEMM via wmma, split-bf16 3-product emulation, inline A convert,
// double-buffered smem, fused el/er/al dot-product epilogue.
#define BM 128
#define BN 128
#define BK 64
#define LDA 72     // 64 + 8 pad (bf16)
#define LDB 136    // 128 + 8 pad
#define CH_AH 0
#define CH_AL (BM*LDA)
#define CH_BH (2*BM*LDA)
#define CH_BL (2*BM*LDA + BK*LDB)
#define CH_ELEM (2*BM*LDA + 2*BK*LDB)            // 35840 bf16 per buffer
#define GS_BYTES (2*CH_ELEM*2)                   // 143360 B
#define LDT 132                                  // fp32 tile ld for epilogue

struct Pref {
    float4 a[8];
    uint4  bh[4], bl[4];
};

__device__ __forceinline__ void gemm_load(Pref& P, const float* __restrict__ feat,
                                          int row0, int col0, int c, int tid) {
#pragma unroll
    for (int u = 0; u < 8; u++) {
        int idx = tid + u * 256;                  // 0..2047
        int r = idx >> 4, kq = idx & 15;
        int row = row0 + r;
        P.a[u] = (row < NN)
            ? *(const float4*)(feat + (size_t)row * 256 + c * 64 + kq * 4)
            : make_float4(0.f, 0.f, 0.f, 0.f);
    }
#pragma unroll
    for (int u = 0; u < 4; u++) {
        int idx = tid + u * 256;                  // 0..1023
        int r = idx >> 4, cq = idx & 15;
        size_t g = (size_t)(c * 64 + r) * 256 + col0 + cq * 8;
        P.bh[u] = *(const uint4*)(g_Wh + g);
        P.bl[u] = *(const uint4*)(g_Wl + g);
    }
}

__device__ __forceinline__ void gemm_store(const Pref& P, __nv_bfloat16* buf, int tid) {
#pragma unroll
    for (int u = 0; u < 8; u++) {
        int idx = tid + u * 256;
        int r = idx >> 4, kq = idx & 15;
        float4 v = P.a[u];
        __nv_bfloat16 hx = __float2bfloat16_rn(v.x), hy = __float2bfloat16_rn(v.y);
        __nv_bfloat16 hz = __float2bfloat16_rn(v.z), hw = __float2bfloat16_rn(v.w);
        __nv_bfloat16* ph = buf + CH_AH + r * LDA + kq * 4;
        __nv_bfloat16* pl = buf + CH_AL + r * LDA + kq * 4;
        *(__nv_bfloat162*)ph       = __nv_bfloat162(hx, hy);
        *(__nv_bfloat162*)(ph + 2) = __nv_bfloat162(hz, hw);
        *(__nv_bfloat162*)pl       = __nv_bfloat162(
            __float2bfloat16_rn(v.x - __bfloat162float(hx)),
            __float2bfloat16_rn(v.y - __bfloat162float(hy)));
        *(__nv_bfloat162*)(pl + 2) = __nv_bfloat162(
            __float2bfloat16_rn(v.z - __bfloat162float(hz)),
            __float2bfloat16_rn(v.w - __bfloat162float(hw)));
    }
#pragma unroll
    for (int u = 0; u < 4; u++) {
        int idx = tid + u * 256;
        int r = idx >> 4, cq = idx & 15;
        *(uint4*)(buf + CH_BH + r * LDB + cq * 8) = P.bh[u];
        *(uint4*)(buf + CH_BL + r * LDB + cq * 8) = P.bl[u];
    }
}

__global__ void __launch_bounds__(256) gemm_wmma_kernel(const float* __restrict__ feat,
                                                        const float* __restrict__ attn_l,
                                                        const float* __restrict__ attn_r,
                                                        const float* __restrict__ hop_attn_l) {
    extern __shared__ __nv_bfloat16 sm[];
    __nv_bfloat16* buf0 = sm;
    __nv_bfloat16* buf1 = sm + CH_ELEM;
    int tid = threadIdx.x, wid = tid >> 5, lane = tid & 31;
    int wy = wid & 3, wx = wid >> 2;              // 4 x 2 warp grid
    int row0 = blockIdx.x * BM, col0 = blockIdx.y * BN;

    wmma::fragment<wmma::accumulator, 16, 16, 16, float> acc[2][4];
#pragma unroll
    for (int i = 0; i < 2; i++)
#pragma unroll
        for (int j = 0; j < 4; j++) wmma::fill_fragment(acc[i][j], 0.f);

    Pref P;
    gemm_load(P, feat, row0, col0, 0, tid);
    gemm_store(P, buf0, tid);
    __syncthreads();

    for (int c = 0; c < 4; c++) {
        __nv_bfloat16* cur = (c & 1) ? buf1 : buf0;
        __nv_bfloat16* nxt = (c & 1) ? buf0 : buf1;
        if (c < 3) gemm_load(P, feat, row0, col0, c + 1, tid);   // LDG overlaps MMA

#pragma unroll
        for (int kk = 0; kk < 4; kk++) {
            wmma::fragment<wmma::matrix_a, 16, 16, 16, __nv_bfloat16, wmma::row_major> fa_h[2], fa_l[2];
            wmma::fragment<wmma::matrix_b, 16, 16, 16, __nv_bfloat16, wmma::row_major> fb_h[4], fb_l[4];
#pragma unroll
            for (int i = 0; i < 2; i++) {
                const __nv_bfloat16* p = cur + CH_AH + (wy * 32 + i * 16) * LDA + kk * 16;
                wmma::load_matrix_sync(fa_h[i], p, LDA);
                wmma::load_matrix_sync(fa_l[i], p + (CH_AL - CH_AH), LDA);
            }
#pragma unroll
            for (int j = 0; j < 4; j++) {
                const __nv_bfloat16* p = cur + CH_BH + (kk * 16) * LDB + wx * 64 + j * 16;
                wmma::load_matrix_sync(fb_h[j], p, LDB);
                wmma::load_matrix_sync(fb_l[j], p + (CH_BL - CH_BH), LDB);
            }
#pragma unroll
            for (int i = 0; i < 2; i++)
#pragma unroll
                for (int j = 0; j < 4; j++) {
                    wmma::mma_sync(acc[i][j], fa_h[i], fb_h[j], acc[i][j]);
                    wmma::mma_sync(acc[i][j], fa_h[i], fb_l[j], acc[i][j]);
                    wmma::mma_sync(acc[i][j], fa_l[i], fb_h[j], acc[i][j]);
                }
        }
        if (c < 3) gemm_store(P, nxt, tid);
        __syncthreads();
    }
    // store 32x64 per warp (g_h row-padded to NPAD, no guards) + smem for dots
    float* smT = (float*)sm;                     // 128 x LDT fp32 tile
#pragma unroll
    for (int i = 0; i < 2; i++)
#pragma unroll
        for (int j = 0; j < 4; j++) {
            float* pg = g_h + (size_t)(row0 + wy * 32 + i * 16) * 256 + col0 + wx * 64 + j * 16;
            wmma::store_matrix_sync(pg, acc[i][j], 256, wmma::mem_row_major);
            wmma::store_matrix_sync(smT + (wy * 32 + i * 16) * LDT + wx * 64 + j * 16,
                                    acc[i][j], LDT, wmma::mem_row_major);
        }
    __syncthreads();

    // fused dots: this CTA's 128 cols = heads {2*by, 2*by+1} complete.
    // warp wid handles rows wid*16..+16; lanes 0-15 head a, 16-31 head b.
    int hsel = lane >> 4;
    int head = blockIdx.y * 2 + hsel;
    int f4 = (lane & 15) * 4;
    float4 wl = *(const float4*)(attn_l     + head * 64 + f4);
    float4 wr = *(const float4*)(attn_r     + head * 64 + f4);
    float4 wh = *(const float4*)(hop_attn_l + head * 64 + f4);
#pragma unroll
    for (int rr = 0; rr < 16; rr++) {
        int r = wid * 16 + rr;
        float4 v = *(const float4*)(smT + r * LDT + lane * 4);
        float pl = v.x * wl.x + v.y * wl.y + v.z * wl.z + v.w * wl.w;
        float pr = v.x * wr.x + v.y * wr.y + v.z * wr.z + v.w * wr.w;
        float ph = v.x * wh.x + v.y * wh.y + v.z * wh.z + v.w * wh.w;
#pragma unroll
        for (int o = 8; o; o >>= 1) {
            pl += __shfl_xor_sync(0xffffffffu, pl, o);
            pr += __shfl_xor_sync(0xffffffffu, pr, o);
            ph += __shfl_xor_sync(0xffffffffu, ph, o);
        }
        int node = row0 + r;
        if ((lane & 15) == 0 && node < NN) {
            g_el[node * 4 + head] = pl;
            g_er[node * 4 + head] = pr;
            g_al[node * 4 + head] = ph;
        }
    }
}

// fused edge pass: logits + exp + both segment sums + degrees
__global__ void edgeAB_kernel(const int* __restrict__ src, const int* __restrict__ dst) {
    int t = blockIdx.x * blockDim.x + threadIdx.x;
    if (t >= EH) return;
    int e = t >> 2, hd = t & 3;
    int s = src[e], d = dst[e];
    float ev = leaky(g_el[s * HH + hd] + g_er[d * HH + hd]);
    g_e[t] = ev;
    float ex = __expf(ev);
    atomicAdd(&g_sum_src[s * HH + hd], ex);
    atomicAdd(&g_sum_dst[d * HH + hd], ex);
    if (hd == 0) { atomicAdd(&g_outdeg[s], 1); atomicAdd(&g_indeg[d], 1); }
}

// degree norms + log of softmax denominators (in-place)
__global__ void norm_kernel() {
    int i = blockIdx.x * blockDim.x + threadIdx.x;
    if (i < NN) {
        g_nout[i] = rsqrtf((float)max(g_outdeg[i], 1));
        g_nin[i]  = sqrtf((float)max(g_indeg[i], 1));
    }
    if (i < NH) {
        g_sum_src[i] = __logf(g_sum_src[i]);
        g_sum_dst[i] = __logf(g_sum_dst[i]);
    }
}

// ---- two-level exclusive scan of indeg -> off ----
__global__ void scanA_kernel() {
    int t = threadIdx.x, lane = t & 31, wid = t >> 5;
    int idx = blockIdx.x * 256 + t;
    int v = (idx < NN) ? g_indeg[idx] : 0;
    int x = v;
#pragma unroll
    for (int o = 1; o < 32; o <<= 1) {
        int y = __shfl_up_sync(0xffffffffu, x, o);
        if (lane >= o) x += y;
    }
    __shared__ int ws[8];
    if (lane == 31) ws[wid] = x;
    __syncthreads();
    if (t < 8) {
        int y = ws[t];
#pragma unroll
        for (int o = 1; o < 8; o <<= 1) {
            int z = __shfl_up_sync(0xffu, y, o);
            if (t >= o) y += z;
        }
        ws[t] = y;
    }
    __syncthreads();
    int incl = x + (wid ? ws[wid - 1] : 0);
    if (idx < NN) g_off[idx] = incl - v;
    if (t == 255) g_bsum[blockIdx.x] = incl;
}

__global__ void scanB_kernel(int nblk) {
    int t = threadIdx.x, lane = t & 31, wid = t >> 5;
    int v = (t < nblk) ? g_bsum[t] : 0;
    int x = v;
#pragma unroll
    for (int o = 1; o < 32; o <<= 1) {
        int y = __shfl_up_sync(0xffffffffu, x, o);
        if (lane >= o) x += y;
    }
    __shared__ int ws[8];
    if (lane == 31) ws[wid] = x;
    __syncthreads();
    if (t < 8) {
        int y = ws[t];
#pragma unroll
        for (int o = 1; o < 8; o <<= 1) {
            int z = __shfl_up_sync(0xffu, y, o);
            if (t >= o) y += z;
        }
        ws[t] = y;
    }
    __syncthreads();
    int incl = x + (wid ? ws[wid - 1] : 0);
    g_boff[t] = incl - v;
}

__global__ void scanC_kernel() {
    int idx = blockIdx.x * 256 + threadIdx.x;
    if (idx < NN) g_off[idx] += g_boff[blockIdx.x];
    if (idx == 0) g_off[NN] = EE;
}

// fused scatter + coefficient: one thread per edge writes CSR slot + 4 head coeffs
__global__ void scatterC_kernel(const int* __restrict__ src, const int* __restrict__ dst,
                                const float* __restrict__ sigma) {
    int e = blockIdx.x * blockDim.x + threadIdx.x;
    if (e >= EE) return;
    int s = src[e], d = dst[e];
    int pos = g_off[d] + atomicAdd(&g_cnt[d], 1);
    g_csr_src[pos] = s;
    float sg = 1.f / (1.f + __expf(-sigma[0]));
    float no = g_nout[s];
    float4 ev = *(const float4*)(g_e + (size_t)e * 4);
    float4 ss = *(const float4*)(g_sum_src + (size_t)s * 4);
    float4 sd = *(const float4*)(g_sum_dst + (size_t)d * 4);
    float4 co;
    co.x = __expf((1.f - sg) * fmaxf(ev.x - ss.x, LCLIP) + sg * fmaxf(ev.x - sd.x, LCLIP)) * no;
    co.y = __expf((1.f - sg) * fmaxf(ev.y - ss.y, LCLIP) + sg * fmaxf(ev.y - sd.y, LCLIP)) * no;
    co.z = __expf((1.f - sg) * fmaxf(ev.z - ss.z, LCLIP) + sg * fmaxf(ev.z - sd.z, LCLIP)) * no;
    co.w = __expf((1.f - sg) * fmaxf(ev.w - ss.w, LCLIP) + sg * fmaxf(ev.w - sd.w, LCLIP)) * no;
    *(float4*)(g_c + (size_t)pos * 4) = co;
}

// one hop: xn[d,h,:] = nin[d] * sum_e c[e,h] * x[src_e,h,:]
// warp per (node, head-pair): lanes 0-15 head 2hp, lanes 16-31 head 2hp+1,
// float4 gathers (512 B contiguous per edge per warp).
__global__ void prop_kernel(int hop) {
    const float* x;
    float* xn;
    if (hop == 0)      { x = g_h;  xn = g_x1; }
    else if (hop == 1) { x = g_x1; xn = g_x2; }
    else               { x = g_x2; xn = g_x3; }
    int pair2 = blockIdx.x * 8 + (threadIdx.x >> 5);      // NN*2 warps
    if (pair2 >= NN * 2) return;
    int lane = threadIdx.x & 31;
    int n = pair2 >> 1, hp = pair2 & 1;
    int hd = hp * 2 + (lane >> 4);
    int fo = hp * 128 + lane * 4;                         // feature offset in 256-row
    int beg = g_off[n], end = g_off[n + 1];
    float4 a = make_float4(0.f, 0.f, 0.f, 0.f);
    int p = beg;
    for (; p + 3 < end; p += 4) {
        int s0 = g_csr_src[p],     s1 = g_csr_src[p + 1];
        int s2 = g_csr_src[p + 2], s3 = g_csr_src[p + 3];
        float c0 = g_c[p * 4 + hd],       c1 = g_c[(p + 1) * 4 + hd];
        float c2 = g_c[(p + 2) * 4 + hd], c3 = g_c[(p + 3) * 4 + hd];
        float4 v0 = *(const float4*)(x + (size_t)s0 * 256 + fo);
        float4 v1 = *(const float4*)(x + (size_t)s1 * 256 + fo);
        float4 v2 = *(const float4*)(x + (size_t)s2 * 256 + fo);
        float4 v3 = *(const float4*)(x + (size_t)s3 * 256 + fo);
        a.x += c0 * v0.x + c1 * v1.x + c2 * v2.x + c3 * v3.x;
        a.y += c0 * v0.y + c1 * v1.y + c2 * v2.y + c3 * v3.y;
        a.z += c0 * v0.z + c1 * v1.z + c2 * v2.z + c3 * v3.z;
        a.w += c0 * v0.w + c1 * v1.w + c2 * v2.w + c3 * v3.w;
    }
    for (; p < end; p++) {
        int s0 = g_csr_src[p];
        float c0 = g_c[p * 4 + hd];
        float4 v0 = *(const float4*)(x + (size_t)s0 * 256 + fo);
        a.x += c0 * v0.x; a.y += c0 * v0.y; a.z += c0 * v0.z; a.w += c0 * v0.w;
    }
    float ni = g_nin[n];
    *(float4*)(xn + (size_t)n * 256 + fo) =
        make_float4(a.x * ni, a.y * ni, a.z * ni, a.w * ni);
}

// hop-attention combine -> output
__global__ void combine_kernel(const float* __restrict__ hop_attn_r,
                               float* __restrict__ out) {
    int pair = blockIdx.x * 8 + (threadIdx.x >> 5);
    if (pair >= NH) return;
    int lane = threadIdx.x & 31;
    int hd = pair & 3;
    float2 wr = ((const float2*)(hop_attn_r + hd * FF))[lane];
    float2 v0 = ((const float2*)(g_h  + (size_t)pair * FF))[lane];
    float2 v1 = ((const float2*)(g_x1 + (size_t)pair * FF))[lane];
    float2 v2 = ((const float2*)(g_x2 + (size_t)pair * FF))[lane];
    float2 v3 = ((const float2*)(g_x3 + (size_t)pair * FF))[lane];
    float d0 = warpAllReduce(v0.x * wr.x + v0.y * wr.y);
    float d1 = warpAllReduce(v1.x * wr.x + v1.y * wr.y);
    float d2 = warpAllReduce(v2.x * wr.x + v2.y * wr.y);
    float d3 = warpAllReduce(v3.x * wr.x + v3.y * wr.y);
    float al = g_al[pair];
    float b0 = leaky(al + d0), b1 = leaky(al + d1);
    float b2 = leaky(al + d2), b3 = leaky(al + d3);
    float m = fmaxf(fmaxf(b0, b1), fmaxf(b2, b3));
    float e0 = __expf(b0 - m), e1 = __expf(b1 - m);
    float e2 = __expf(b2 - m), e3 = __expf(b3 - m);
    float inv = 1.f / (e0 + e1 + e2 + e3);
    e0 *= inv; e1 *= inv; e2 *= inv; e3 *= inv;
    float2 r;
    r.x = v0.x * e0 + v1.x * e1 + v2.x * e2 + v3.x * e3;
    r.y = v0.y * e0 + v1.y * e1 + v2.y * e2 + v3.y * e3;
    ((float2*)(out + (size_t)pair * FF))[lane] = r;
}

// ---------------- launch ----------------------------------------------------
extern "C" void kernel_launch(void* const* d_in, const int* in_sizes, int n_in,
                              void* d_out, int out_size) {
    const float* feat  = (const float*)d_in[0];
    const int*   src   = (const int*)d_in[1];
    const int*   dst   = (const int*)d_in[2];
    const float* W     = (const float*)d_in[3];
    const float* attn_l     = (const float*)d_in[4];
    const float* attn_r     = (const float*)d_in[5];
    const float* hop_attn_l = (const float*)d_in[6];
    const float* hop_attn_r = (const float*)d_in[7];
    const float* sigma      = (const float*)d_in[8];
    float* out = (float*)d_out;

    const int NBLK = (NN + 255) / 256;   // 196

    cudaFuncSetAttribute(gemm_wmma_kernel,
                         cudaFuncAttributeMaxDynamicSharedMemorySize, GS_BYTES);

    init_kernel<<<(NH + 255) / 256, 256>>>();
    convertW_kernel<<<64, 256>>>(W);
    gemm_wmma_kernel<<<dim3(NPAD / BM, 2), 256, GS_BYTES>>>(feat, attn_l, attn_r, hop_attn_l);
    edgeAB_kernel<<<(EH + 255) / 256, 256>>>(src, dst);
    norm_kernel<<<(NH + 255) / 256, 256>>>();
    scanA_kernel<<<NBLK, 256>>>();
    scanB_kernel<<<1, 256>>>(NBLK);
    scanC_kernel<<<NBLK, 256>>>();
    scatterC_kernel<<<(EE + 255) / 256, 256>>>(src, dst, sigma);
    prop_kernel<<<(NN * 2 + 7) / 8, 256>>>(0);
    prop_kernel<<<(NN * 2 + 7) / 8, 256>>>(1);
    prop_kernel<<<(NN * 2 + 7) / 8, 256>>>(2);
    combine_kernel<<<(NH + 7) / 8, 256>>>(hop_attn_r, out);
}

// round 8
// speedup vs baseline: 1.1149x; 1.1149x over previous
#include <cuda_runtime.h>
#include <cuda_bf16.h>
#include <mma.h>
#include <math.h>
#include <stdint.h>

using namespace nvcuda;

#define NN 50000
#define NPAD 50048            // 391 * 128
#define EE 800000
#define INF_ 256
#define HH 4
#define FF 64
#define NH (NN*HH)            // 200000
#define EH (EE*HH)            // 3200000
#define SLOPE 0.2f
#define LCLIP (-23.0258509f)  // log(1e-10)

// ---------------- scratch (static device globals; no allocation) ------------
__device__ float g_h [NPAD*HH*FF];   // padded rows for guard-free wmma stores
__device__ float g_x1[NN*HH*FF];
__device__ float g_x2[NN*HH*FF];
__device__ float g_x3[NN*HH*FF];
__device__ float g_el[NH], g_er[NH], g_al[NH];
__device__ float g_sum_src[NH], g_sum_dst[NH];   // exp-sums, then logs in-place
__device__ float g_e[EH];      // leaky_relu(el[src]+er[dst])
__device__ float g_c[EE*HH];   // per-edge coefficient, CSR order: [pos][hd]
__device__ int   g_indeg[NN], g_outdeg[NN], g_cnt[NN];
__device__ int   g_off[NN+1];
__device__ int   g_csr_src[EE];
__device__ float g_nin[NN], g_nout[NN];
__device__ int   g_bsum[256], g_boff[256];
__device__ __nv_bfloat16 g_Wh[256*256];   // [k][n] row-major, split hi/lo
__device__ __nv_bfloat16 g_Wl[256*256];

// ---------------- helpers ---------------------------------------------------
__device__ __forceinline__ float leaky(float x) { return x > 0.f ? x : SLOPE * x; }

__device__ __forceinline__ float warpAllReduce(float v) {
#pragma unroll
    for (int o = 16; o; o >>= 1) v += __shfl_xor_sync(0xffffffffu, v, o);
    return v;
}

// ---------------- kernels ---------------------------------------------------
__global__ void init_kernel() {
    int i = blockIdx.x * blockDim.x + threadIdx.x;
    if (i < NN) { g_indeg[i] = 0; g_outdeg[i] = 0; g_cnt[i] = 0; }
    if (i < NH) { g_sum_src[i] = 0.f; g_sum_dst[i] = 0.f; }
}

// W -> split bf16 hi/lo, same [k][n] layout
__global__ void convertW_kernel(const float* __restrict__ W) {
    int idx = blockIdx.x * 256 + threadIdx.x;      // 65536/4 threads
    if (idx >= 64 * 256) return;
    float4 v = ((const float4*)W)[idx];
    __nv_bfloat16 hx = __float2bfloat16_rn(v.x), hy = __float2bfloat16_rn(v.y);
    __nv_bfloat16 hz = __float2bfloat16_rn(v.z), hw = __float2bfloat16_rn(v.w);
    ((__nv_bfloat162*)g_Wh)[idx * 2]     = __nv_bfloat162(hx, hy);
    ((__nv_bfloat162*)g_Wh)[idx * 2 + 1] = __nv_bfloat162(hz, hw);
    ((__nv_bfloat162*)g_Wl)[idx * 2]     = __nv_bfloat162(
        __float2bfloat16_rn(v.x - __bfloat162float(hx)),
        __float2bfloat16_rn(v.y - __bfloat162float(hy)));
    ((__nv_bfloat162*)g_Wl)[idx * 2 + 1] = __nv_bfloat162(
        __float2bfloat16_rn(v.z - __bfloat162float(hz)),
        __float2bfloat16_rn(v.w - __bfloat162float(hw)));
}

// tensor-core GEMM via wmma, split-bf16 3-product emulation, inline A convert,
// double-buffered smem, fused el/er/al dot-product epilogue.
#define BM 128
#define BN 128
#define BK 64
#define LDA 72     // 64 + 8 pad (bf16)
#define LDB 136    // 128 + 8 pad
#define CH_AH 0
#define CH_AL (BM*LDA)
#define CH_BH (2*BM*LDA)
#define CH_BL (2*BM*LDA + BK*LDB)
#define CH_ELEM (2*BM*LDA + 2*BK*LDB)            // 35840 bf16 per buffer
#define GS_BYTES (2*CH_ELEM*2)                   // 143360 B
#define LDT 132                                  // fp32 tile ld for epilogue

struct Pref {
    float4 a[8];
    uint4  bh[4], bl[4];
};

__device__ __forceinline__ void gemm_load(Pref& P, const float* __restrict__ feat,
                                          int row0, int col0, int c, int tid) {
#pragma unroll
    for (int u = 0; u < 8; u++) {
        int idx = tid + u * 256;                  // 0..2047
        int r = idx >> 4, kq = idx & 15;
        int row = row0 + r;
        P.a[u] = (row < NN)
            ? *(const float4*)(feat + (size_t)row * 256 + c * 64 + kq * 4)
            : make_float4(0.f, 0.f, 0.f, 0.f);
    }
#pragma unroll
    for (int u = 0; u < 4; u++) {
        int idx = tid + u * 256;                  // 0..1023
        int r = idx >> 4, cq = idx & 15;
        size_t g = (size_t)(c * 64 + r) * 256 + col0 + cq * 8;
        P.bh[u] = *(const uint4*)(g_Wh + g);
        P.bl[u] = *(const uint4*)(g_Wl + g);
    }
}

__device__ __forceinline__ void gemm_store(const Pref& P, __nv_bfloat16* buf, int tid) {
#pragma unroll
    for (int u = 0; u < 8; u++) {
        int idx = tid + u * 256;
        int r = idx >> 4, kq = idx & 15;
        float4 v = P.a[u];
        __nv_bfloat16 hx = __float2bfloat16_rn(v.x), hy = __float2bfloat16_rn(v.y);
        __nv_bfloat16 hz = __float2bfloat16_rn(v.z), hw = __float2bfloat16_rn(v.w);
        __nv_bfloat16* ph = buf + CH_AH + r * LDA + kq * 4;
        __nv_bfloat16* pl = buf + CH_AL + r * LDA + kq * 4;
        *(__nv_bfloat162*)ph       = __nv_bfloat162(hx, hy);
        *(__nv_bfloat162*)(ph + 2) = __nv_bfloat162(hz, hw);
        *(__nv_bfloat162*)pl       = __nv_bfloat162(
            __float2bfloat16_rn(v.x - __bfloat162float(hx)),
            __float2bfloat16_rn(v.y - __bfloat162float(hy)));
        *(__nv_bfloat162*)(pl + 2) = __nv_bfloat162(
            __float2bfloat16_rn(v.z - __bfloat162float(hz)),
            __float2bfloat16_rn(v.w - __bfloat162float(hw)));
    }
#pragma unroll
    for (int u = 0; u < 4; u++) {
        int idx = tid + u * 256;
        int r = idx >> 4, cq = idx & 15;
        *(uint4*)(buf + CH_BH + r * LDB + cq * 8) = P.bh[u];
        *(uint4*)(buf + CH_BL + r * LDB + cq * 8) = P.bl[u];
    }
}

__global__ void __launch_bounds__(256) gemm_wmma_kernel(const float* __restrict__ feat,
                                                        const float* __restrict__ attn_l,
                                                        const float* __restrict__ attn_r,
                                                        const float* __restrict__ hop_attn_l) {
    extern __shared__ __nv_bfloat16 sm[];
    __nv_bfloat16* buf0 = sm;
    __nv_bfloat16* buf1 = sm + CH_ELEM;
    int tid = threadIdx.x, wid = tid >> 5, lane = tid & 31;
    int wy = wid & 3, wx = wid >> 2;              // 4 x 2 warp grid
    int row0 = blockIdx.x * BM, col0 = blockIdx.y * BN;

    wmma::fragment<wmma::accumulator, 16, 16, 16, float> acc[2][4];
#pragma unroll
    for (int i = 0; i < 2; i++)
#pragma unroll
        for (int j = 0; j < 4; j++) wmma::fill_fragment(acc[i][j], 0.f);

    Pref P;
    gemm_load(P, feat, row0, col0, 0, tid);
    gemm_store(P, buf0, tid);
    __syncthreads();

    for (int c = 0; c < 4; c++) {
        __nv_bfloat16* cur = (c & 1) ? buf1 : buf0;
        __nv_bfloat16* nxt = (c & 1) ? buf0 : buf1;
        if (c < 3) gemm_load(P, feat, row0, col0, c + 1, tid);   // LDG overlaps MMA

#pragma unroll
        for (int kk = 0; kk < 4; kk++) {
            wmma::fragment<wmma::matrix_a, 16, 16, 16, __nv_bfloat16, wmma::row_major> fa_h[2], fa_l[2];
            wmma::fragment<wmma::matrix_b, 16, 16, 16, __nv_bfloat16, wmma::row_major> fb_h[4], fb_l[4];
#pragma unroll
            for (int i = 0; i < 2; i++) {
                const __nv_bfloat16* p = cur + CH_AH + (wy * 32 + i * 16) * LDA + kk * 16;
                wmma::load_matrix_sync(fa_h[i], p, LDA);
                wmma::load_matrix_sync(fa_l[i], p + (CH_AL - CH_AH), LDA);
            }
#pragma unroll
            for (int j = 0; j < 4; j++) {
                const __nv_bfloat16* p = cur + CH_BH + (kk * 16) * LDB + wx * 64 + j * 16;
                wmma::load_matrix_sync(fb_h[j], p, LDB);
                wmma::load_matrix_sync(fb_l[j], p + (CH_BL - CH_BH), LDB);
            }
#pragma unroll
            for (int i = 0; i < 2; i++)
#pragma unroll
                for (int j = 0; j < 4; j++) {
                    wmma::mma_sync(acc[i][j], fa_h[i], fb_h[j], acc[i][j]);
                    wmma::mma_sync(acc[i][j], fa_h[i], fb_l[j], acc[i][j]);
                    wmma::mma_sync(acc[i][j], fa_l[i], fb_h[j], acc[i][j]);
                }
        }
        if (c < 3) gemm_store(P, nxt, tid);
        __syncthreads();
    }
    // store 32x64 per warp (g_h row-padded to NPAD, no guards) + smem for dots
    float* smT = (float*)sm;                     // 128 x LDT fp32 tile
#pragma unroll
    for (int i = 0; i < 2; i++)
#pragma unroll
        for (int j = 0; j < 4; j++) {
            float* pg = g_h + (size_t)(row0 + wy * 32 + i * 16) * 256 + col0 + wx * 64 + j * 16;
            wmma::store_matrix_sync(pg, acc[i][j], 256, wmma::mem_row_major);
            wmma::store_matrix_sync(smT + (wy * 32 + i * 16) * LDT + wx * 64 + j * 16,
                                    acc[i][j], LDT, wmma::mem_row_major);
        }
    __syncthreads();

    // fused dots: this CTA's 128 cols = heads {2*by, 2*by+1} complete.
    // warp wid handles rows wid*16..+16; lanes 0-15 head a, 16-31 head b.
    int hsel = lane >> 4;
    int head = blockIdx.y * 2 + hsel;
    int f4 = (lane & 15) * 4;
    float4 wl = *(const float4*)(attn_l     + head * 64 + f4);
    float4 wr = *(const float4*)(attn_r     + head * 64 + f4);
    float4 wh = *(const float4*)(hop_attn_l + head * 64 + f4);
#pragma unroll
    for (int rr = 0; rr < 16; rr++) {
        int r = wid * 16 + rr;
        float4 v = *(const float4*)(smT + r * LDT + lane * 4);
        float pl = v.x * wl.x + v.y * wl.y + v.z * wl.z + v.w * wl.w;
        float pr = v.x * wr.x + v.y * wr.y + v.z * wr.z + v.w * wr.w;
        float ph = v.x * wh.x + v.y * wh.y + v.z * wh.z + v.w * wh.w;
#pragma unroll
        for (int o = 8; o; o >>= 1) {
            pl += __shfl_xor_sync(0xffffffffu, pl, o);
            pr += __shfl_xor_sync(0xffffffffu, pr, o);
            ph += __shfl_xor_sync(0xffffffffu, ph, o);
        }
        int node = row0 + r;
        if ((lane & 15) == 0 && node < NN) {
            g_el[node * 4 + head] = pl;
            g_er[node * 4 + head] = pr;
            g_al[node * 4 + head] = ph;
        }
    }
}

// fused edge pass: logits + exp + both segment sums + degrees
__global__ void edgeAB_kernel(const int* __restrict__ src, const int* __restrict__ dst) {
    int t = blockIdx.x * blockDim.x + threadIdx.x;
    if (t >= EH) return;
    int e = t >> 2, hd = t & 3;
    int s = src[e], d = dst[e];
    float ev = leaky(g_el[s * HH + hd] + g_er[d * HH + hd]);
    g_e[t] = ev;
    float ex = __expf(ev);
    atomicAdd(&g_sum_src[s * HH + hd], ex);
    atomicAdd(&g_sum_dst[d * HH + hd], ex);
    if (hd == 0) { atomicAdd(&g_outdeg[s], 1); atomicAdd(&g_indeg[d], 1); }
}

// degree norms + log of softmax denominators (in-place)
__global__ void norm_kernel() {
    int i = blockIdx.x * blockDim.x + threadIdx.x;
    if (i < NN) {
        g_nout[i] = rsqrtf((float)max(g_outdeg[i], 1));
        g_nin[i]  = sqrtf((float)max(g_indeg[i], 1));
    }
    if (i < NH) {
        g_sum_src[i] = __logf(g_sum_src[i]);
        g_sum_dst[i] = __logf(g_sum_dst[i]);
    }
}

// ---- two-level exclusive scan of indeg -> off ----
__global__ void scanA_kernel() {
    int t = threadIdx.x, lane = t & 31, wid = t >> 5;
    int idx = blockIdx.x * 256 + t;
    int v = (idx < NN) ? g_indeg[idx] : 0;
    int x = v;
#pragma unroll
    for (int o = 1; o < 32; o <<= 1) {
        int y = __shfl_up_sync(0xffffffffu, x, o);
        if (lane >= o) x += y;
    }
    __shared__ int ws[8];
    if (lane == 31) ws[wid] = x;
    __syncthreads();
    if (t < 8) {
        int y = ws[t];
#pragma unroll
        for (int o = 1; o < 8; o <<= 1) {
            int z = __shfl_up_sync(0xffu, y, o);
            if (t >= o) y += z;
        }
        ws[t] = y;
    }
    __syncthreads();
    int incl = x + (wid ? ws[wid - 1] : 0);
    if (idx < NN) g_off[idx] = incl - v;
    if (t == 255) g_bsum[blockIdx.x] = incl;
}

__global__ void scanB_kernel(int nblk) {
    int t = threadIdx.x, lane = t & 31, wid = t >> 5;
    int v = (t < nblk) ? g_bsum[t] : 0;
    int x = v;
#pragma unroll
    for (int o = 1; o < 32; o <<= 1) {
        int y = __shfl_up_sync(0xffffffffu, x, o);
        if (lane >= o) x += y;
    }
    __shared__ int ws[8];
    if (lane == 31) ws[wid] = x;
    __syncthreads();
    if (t < 8) {
        int y = ws[t];
#pragma unroll
        for (int o = 1; o < 8; o <<= 1) {
            int z = __shfl_up_sync(0xffu, y, o);
            if (t >= o) y += z;
        }
        ws[t] = y;
    }
    __syncthreads();
    int incl = x + (wid ? ws[wid - 1] : 0);
    g_boff[t] = incl - v;
}

__global__ void scanC_kernel() {
    int idx = blockIdx.x * 256 + threadIdx.x;
    if (idx < NN) g_off[idx] += g_boff[blockIdx.x];
    if (idx == 0) g_off[NN] = EE;
}

// fused scatter + coefficient: one thread per edge writes CSR slot + 4 head coeffs
__global__ void scatterC_kernel(const int* __restrict__ src, const int* __restrict__ dst,
                                const float* __restrict__ sigma) {
    int e = blockIdx.x * blockDim.x + threadIdx.x;
    if (e >= EE) return;
    int s = src[e], d = dst[e];
    int pos = g_off[d] + atomicAdd(&g_cnt[d], 1);
    g_csr_src[pos] = s;
    float sg = 1.f / (1.f + __expf(-sigma[0]));
    float no = g_nout[s];
    float4 ev = *(const float4*)(g_e + (size_t)e * 4);
    float4 ss = *(const float4*)(g_sum_src + (size_t)s * 4);
    float4 sd = *(const float4*)(g_sum_dst + (size_t)d * 4);
    float4 co;
    co.x = __expf((1.f - sg) * fmaxf(ev.x - ss.x, LCLIP) + sg * fmaxf(ev.x - sd.x, LCLIP)) * no;
    co.y = __expf((1.f - sg) * fmaxf(ev.y - ss.y, LCLIP) + sg * fmaxf(ev.y - sd.y, LCLIP)) * no;
    co.z = __expf((1.f - sg) * fmaxf(ev.z - ss.z, LCLIP) + sg * fmaxf(ev.z - sd.z, LCLIP)) * no;
    co.w = __expf((1.f - sg) * fmaxf(ev.w - ss.w, LCLIP) + sg * fmaxf(ev.w - sd.w, LCLIP)) * no;
    *(float4*)(g_c + (size_t)pos * 4) = co;
}

// one hop: xn[d,h,:] = nin[d] * sum_e c[e,h] * x[src_e,h,:]
// R6 form: one warp per (node, head), float2 gathers, 4-way unroll (200k warps)
__global__ void prop_kernel(int hop) {
    const float* x;
    float* xn;
    if (hop == 0)      { x = g_h;  xn = g_x1; }
    else if (hop == 1) { x = g_x1; xn = g_x2; }
    else               { x = g_x2; xn = g_x3; }
    int pair = blockIdx.x * 8 + (threadIdx.x >> 5);
    if (pair >= NH) return;
    int lane = threadIdx.x & 31;
    int n = pair >> 2, hd = pair & 3;
    int beg = g_off[n], end = g_off[n + 1];
    float ax = 0.f, ay = 0.f;
    int p = beg;
    for (; p + 3 < end; p += 4) {
        int s0 = g_csr_src[p],     s1 = g_csr_src[p + 1];
        int s2 = g_csr_src[p + 2], s3 = g_csr_src[p + 3];
        float c0 = g_c[p * 4 + hd],       c1 = g_c[(p + 1) * 4 + hd];
        float c2 = g_c[(p + 2) * 4 + hd], c3 = g_c[(p + 3) * 4 + hd];
        float2 v0 = ((const float2*)(x + (size_t)(s0 * 4 + hd) * FF))[lane];
        float2 v1 = ((const float2*)(x + (size_t)(s1 * 4 + hd) * FF))[lane];
        float2 v2 = ((const float2*)(x + (size_t)(s2 * 4 + hd) * FF))[lane];
        float2 v3 = ((const float2*)(x + (size_t)(s3 * 4 + hd) * FF))[lane];
        ax += c0 * v0.x + c1 * v1.x + c2 * v2.x + c3 * v3.x;
        ay += c0 * v0.y + c1 * v1.y + c2 * v2.y + c3 * v3.y;
    }
    for (; p < end; p++) {
        int s0 = g_csr_src[p];
        float c0 = g_c[p * 4 + hd];
        float2 v0 = ((const float2*)(x + (size_t)(s0 * 4 + hd) * FF))[lane];
        ax += c0 * v0.x;
        ay += c0 * v0.y;
    }
    float ni = g_nin[n];
    ((float2*)(xn + (size_t)pair * FF))[lane] = make_float2(ax * ni, ay * ni);
}

// hop-attention combine -> output
__global__ void combine_kernel(const float* __restrict__ hop_attn_r,
                               float* __restrict__ out) {
    int pair = blockIdx.x * 8 + (threadIdx.x >> 5);
    if (pair >= NH) return;
    int lane = threadIdx.x & 31;
    int hd = pair & 3;
    float2 wr = ((const float2*)(hop_attn_r + hd * FF))[lane];
    float2 v0 = ((const float2*)(g_h  + (size_t)pair * FF))[lane];
    float2 v1 = ((const float2*)(g_x1 + (size_t)pair * FF))[lane];
    float2 v2 = ((const float2*)(g_x2 + (size_t)pair * FF))[lane];
    float2 v3 = ((const float2*)(g_x3 + (size_t)pair * FF))[lane];
    float d0 = warpAllReduce(v0.x * wr.x + v0.y * wr.y);
    float d1 = warpAllReduce(v1.x * wr.x + v1.y * wr.y);
    float d2 = warpAllReduce(v2.x * wr.x + v2.y * wr.y);
    float d3 = warpAllReduce(v3.x * wr.x + v3.y * wr.y);
    float al = g_al[pair];
    float b0 = leaky(al + d0), b1 = leaky(al + d1);
    float b2 = leaky(al + d2), b3 = leaky(al + d3);
    float m = fmaxf(fmaxf(b0, b1), fmaxf(b2, b3));
    float e0 = __expf(b0 - m), e1 = __expf(b1 - m);
    float e2 = __expf(b2 - m), e3 = __expf(b3 - m);
    float inv = 1.f / (e0 + e1 + e2 + e3);
    e0 *= inv; e1 *= inv; e2 *= inv; e3 *= inv;
    float2 r;
    r.x = v0.x * e0 + v1.x * e1 + v2.x * e2 + v3.x * e3;
    r.y = v0.y * e0 + v1.y * e1 + v2.y * e2 + v3.y * e3;
    ((float2*)(out + (size_t)pair * FF))[lane] = r;
}

// ---------------- launch ----------------------------------------------------
extern "C" void kernel_launch(void* const* d_in, const int* in_sizes, int n_in,
                              void* d_out, int out_size) {
    const float* feat  = (const float*)d_in[0];
    const int*   src   = (const int*)d_in[1];
    const int*   dst   = (const int*)d_in[2];
    const float* W     = (const float*)d_in[3];
    const float* attn_l     = (const float*)d_in[4];
    const float* attn_r     = (const float*)d_in[5];
    const float* hop_attn_l = (const float*)d_in[6];
    const float* hop_attn_r = (const float*)d_in[7];
    const float* sigma      = (const float*)d_in[8];
    float* out = (float*)d_out;

    const int NBLK = (NN + 255) / 256;   // 196

    cudaFuncSetAttribute(gemm_wmma_kernel,
                         cudaFuncAttributeMaxDynamicSharedMemorySize, GS_BYTES);

    init_kernel<<<(NH + 255) / 256, 256>>>();
    convertW_kernel<<<64, 256>>>(W);
    gemm_wmma_kernel<<<dim3(NPAD / BM, 2), 256, GS_BYTES>>>(feat, attn_l, attn_r, hop_attn_l);
    edgeAB_kernel<<<(EH + 255) / 256, 256>>>(src, dst);
    norm_kernel<<<(NH + 255) / 256, 256>>>();
    scanA_kernel<<<NBLK, 256>>>();
    scanB_kernel<<<1, 256>>>(NBLK);
    scanC_kernel<<<NBLK, 256>>>();
    scatterC_kernel<<<(EE + 255) / 256, 256>>>(src, dst, sigma);
    prop_kernel<<<(NH + 7) / 8, 256>>>(0);
    prop_kernel<<<(NH + 7) / 8, 256>>>(1);
    prop_kernel<<<(NH + 7) / 8, 256>>>(2);
    combine_kernel<<<(NH + 7) / 8, 256>>>(hop_attn_r, out);
}

// round 9
// speedup vs baseline: 1.3495x; 1.2104x over previous
#include <cuda_runtime.h>
#include <cuda_bf16.h>
#include <mma.h>
#include <math.h>
#include <stdint.h>

using namespace nvcuda;

#define NN 50000
#define NPAD 50048            // 391 * 128
#define EE 800000
#define INF_ 256
#define HH 4
#define FF 64
#define NH (NN*HH)            // 200000
#define EH (EE*HH)            // 3200000
#define SLOPE 0.2f
#define LCLIP (-23.0258509f)  // log(1e-10)

// ---------------- scratch (static device globals; no allocation) ------------
__device__ float g_h [NPAD*HH*FF];   // padded rows for guard-free wmma stores
__device__ float g_x1[NN*HH*FF];
__device__ float g_x2[NN*HH*FF];
__device__ float g_el[NH], g_er[NH], g_al[NH];
__device__ float g_sum_src[NH], g_sum_dst[NH];   // exp-sums, then logs in-place
__device__ float g_e[EH];      // leaky_relu(el[src]+er[dst])
__device__ float g_c[EE*HH];   // per-edge coefficient, CSR order: [pos][hd]
__device__ int   g_indeg[NN], g_outdeg[NN], g_cnt[NN];
__device__ int   g_off[NN+1];
__device__ int   g_csr_src[EE];
__device__ float g_nin[NN], g_nout[NN];
__device__ int   g_bsum[256], g_boff[256];
__device__ __nv_bfloat16 g_Wh[256*256];   // [k][n] row-major, split hi/lo
__device__ __nv_bfloat16 g_Wl[256*256];

// ---------------- helpers ---------------------------------------------------
__device__ __forceinline__ float leaky(float x) { return x > 0.f ? x : SLOPE * x; }

__device__ __forceinline__ float warpAllReduce(float v) {
#pragma unroll
    for (int o = 16; o; o >>= 1) v += __shfl_xor_sync(0xffffffffu, v, o);
    return v;
}

// ---------------- kernels ---------------------------------------------------
__global__ void init_kernel() {
    int i = blockIdx.x * blockDim.x + threadIdx.x;
    if (i < NN) { g_indeg[i] = 0; g_outdeg[i] = 0; g_cnt[i] = 0; }
    if (i < NH) { g_sum_src[i] = 0.f; g_sum_dst[i] = 0.f; }
}

// W -> split bf16 hi/lo, same [k][n] layout
__global__ void convertW_kernel(const float* __restrict__ W) {
    int idx = blockIdx.x * 256 + threadIdx.x;      // 65536/4 threads
    if (idx >= 64 * 256) return;
    float4 v = ((const float4*)W)[idx];
    __nv_bfloat16 hx = __float2bfloat16_rn(v.x), hy = __float2bfloat16_rn(v.y);
    __nv_bfloat16 hz = __float2bfloat16_rn(v.z), hw = __float2bfloat16_rn(v.w);
    ((__nv_bfloat162*)g_Wh)[idx * 2]     = __nv_bfloat162(hx, hy);
    ((__nv_bfloat162*)g_Wh)[idx * 2 + 1] = __nv_bfloat162(hz, hw);
    ((__nv_bfloat162*)g_Wl)[idx * 2]     = __nv_bfloat162(
        __float2bfloat16_rn(v.x - __bfloat162float(hx)),
        __float2bfloat16_rn(v.y - __bfloat162float(hy)));
    ((__nv_bfloat162*)g_Wl)[idx * 2 + 1] = __nv_bfloat162(
        __float2bfloat16_rn(v.z - __bfloat162float(hz)),
        __float2bfloat16_rn(v.w - __bfloat162float(hw)));
}

// tensor-core GEMM via wmma, split-bf16 3-product emulation, inline A convert,
// double-buffered smem, fused el/er/al dot-product epilogue.
#define BM 128
#define BN 128
#define BK 64
#define LDA 72     // 64 + 8 pad (bf16)
#define LDB 136    // 128 + 8 pad
#define CH_AH 0
#define CH_AL (BM*LDA)
#define CH_BH (2*BM*LDA)
#define CH_BL (2*BM*LDA + BK*LDB)
#define CH_ELEM (2*BM*LDA + 2*BK*LDB)            // 35840 bf16 per buffer
#define GS_BYTES (2*CH_ELEM*2)                   // 143360 B
#define LDT 132                                  // fp32 tile ld for epilogue

struct Pref {
    float4 a[8];
    uint4  bh[4], bl[4];
};

__device__ __forceinline__ void gemm_load(Pref& P, const float* __restrict__ feat,
                                          int row0, int col0, int c, int tid) {
#pragma unroll
    for (int u = 0; u < 8; u++) {
        int idx = tid + u * 256;                  // 0..2047
        int r = idx >> 4, kq = idx & 15;
        int row = row0 + r;
        P.a[u] = (row < NN)
            ? *(const float4*)(feat + (size_t)row * 256 + c * 64 + kq * 4)
            : make_float4(0.f, 0.f, 0.f, 0.f);
    }
#pragma unroll
    for (int u = 0; u < 4; u++) {
        int idx = tid + u * 256;                  // 0..1023
        int r = idx >> 4, cq = idx & 15;
        size_t g = (size_t)(c * 64 + r) * 256 + col0 + cq * 8;
        P.bh[u] = *(const uint4*)(g_Wh + g);
        P.bl[u] = *(const uint4*)(g_Wl + g);
    }
}

__device__ __forceinline__ void gemm_store(const Pref& P, __nv_bfloat16* buf, int tid) {
#pragma unroll
    for (int u = 0; u < 8; u++) {
        int idx = tid + u * 256;
        int r = idx >> 4, kq = idx & 15;
        float4 v = P.a[u];
        __nv_bfloat16 hx = __float2bfloat16_rn(v.x), hy = __float2bfloat16_rn(v.y);
        __nv_bfloat16 hz = __float2bfloat16_rn(v.z), hw = __float2bfloat16_rn(v.w);
        __nv_bfloat16* ph = buf + CH_AH + r * LDA + kq * 4;
        __nv_bfloat16* pl = buf + CH_AL + r * LDA + kq * 4;
        *(__nv_bfloat162*)ph       = __nv_bfloat162(hx, hy);
        *(__nv_bfloat162*)(ph + 2) = __nv_bfloat162(hz, hw);
        *(__nv_bfloat162*)pl       = __nv_bfloat162(
            __float2bfloat16_rn(v.x - __bfloat162float(hx)),
            __float2bfloat16_rn(v.y - __bfloat162float(hy)));
        *(__nv_bfloat162*)(pl + 2) = __nv_bfloat162(
            __float2bfloat16_rn(v.z - __bfloat162float(hz)),
            __float2bfloat16_rn(v.w - __bfloat162float(hw)));
    }
#pragma unroll
    for (int u = 0; u < 4; u++) {
        int idx = tid + u * 256;
        int r = idx >> 4, cq = idx & 15;
        *(uint4*)(buf + CH_BH + r * LDB + cq * 8) = P.bh[u];
        *(uint4*)(buf + CH_BL + r * LDB + cq * 8) = P.bl[u];
    }
}

__global__ void __launch_bounds__(256) gemm_wmma_kernel(const float* __restrict__ feat,
                                                        const float* __restrict__ attn_l,
                                                        const float* __restrict__ attn_r,
                                                        const float* __restrict__ hop_attn_l) {
    extern __shared__ __nv_bfloat16 sm[];
    __nv_bfloat16* buf0 = sm;
    __nv_bfloat16* buf1 = sm + CH_ELEM;
    int tid = threadIdx.x, wid = tid >> 5, lane = tid & 31;
    int wy = wid & 3, wx = wid >> 2;              // 4 x 2 warp grid
    int row0 = blockIdx.x * BM, col0 = blockIdx.y * BN;

    wmma::fragment<wmma::accumulator, 16, 16, 16, float> acc[2][4];
#pragma unroll
    for (int i = 0; i < 2; i++)
#pragma unroll
        for (int j = 0; j < 4; j++) wmma::fill_fragment(acc[i][j], 0.f);

    Pref P;
    gemm_load(P, feat, row0, col0, 0, tid);
    gemm_store(P, buf0, tid);
    __syncthreads();

    for (int c = 0; c < 4; c++) {
        __nv_bfloat16* cur = (c & 1) ? buf1 : buf0;
        __nv_bfloat16* nxt = (c & 1) ? buf0 : buf1;
        if (c < 3) gemm_load(P, feat, row0, col0, c + 1, tid);   // LDG overlaps MMA

#pragma unroll
        for (int kk = 0; kk < 4; kk++) {
            wmma::fragment<wmma::matrix_a, 16, 16, 16, __nv_bfloat16, wmma::row_major> fa_h[2], fa_l[2];
            wmma::fragment<wmma::matrix_b, 16, 16, 16, __nv_bfloat16, wmma::row_major> fb_h[4], fb_l[4];
#pragma unroll
            for (int i = 0; i < 2; i++) {
                const __nv_bfloat16* p = cur + CH_AH + (wy * 32 + i * 16) * LDA + kk * 16;
                wmma::load_matrix_sync(fa_h[i], p, LDA);
                wmma::load_matrix_sync(fa_l[i], p + (CH_AL - CH_AH), LDA);
            }
#pragma unroll
            for (int j = 0; j < 4; j++) {
                const __nv_bfloat16* p = cur + CH_BH + (kk * 16) * LDB + wx * 64 + j * 16;
                wmma::load_matrix_sync(fb_h[j], p, LDB);
                wmma::load_matrix_sync(fb_l[j], p + (CH_BL - CH_BH), LDB);
            }
#pragma unroll
            for (int i = 0; i < 2; i++)
#pragma unroll
                for (int j = 0; j < 4; j++) {
                    wmma::mma_sync(acc[i][j], fa_h[i], fb_h[j], acc[i][j]);
                    wmma::mma_sync(acc[i][j], fa_h[i], fb_l[j], acc[i][j]);
                    wmma::mma_sync(acc[i][j], fa_l[i], fb_h[j], acc[i][j]);
                }
        }
        if (c < 3) gemm_store(P, nxt, tid);
        __syncthreads();
    }
    // store 32x64 per warp (g_h row-padded to NPAD, no guards) + smem for dots
    float* smT = (float*)sm;                     // 128 x LDT fp32 tile
#pragma unroll
    for (int i = 0; i < 2; i++)
#pragma unroll
        for (int j = 0; j < 4; j++) {
            float* pg = g_h + (size_t)(row0 + wy * 32 + i * 16) * 256 + col0 + wx * 64 + j * 16;
            wmma::store_matrix_sync(pg, acc[i][j], 256, wmma::mem_row_major);
            wmma::store_matrix_sync(smT + (wy * 32 + i * 16) * LDT + wx * 64 + j * 16,
                                    acc[i][j], LDT, wmma::mem_row_major);
        }
    __syncthreads();

    // fused dots: this CTA's 128 cols = heads {2*by, 2*by+1} complete.
    int hsel = lane >> 4;
    int head = blockIdx.y * 2 + hsel;
    int f4 = (lane & 15) * 4;
    float4 wl = *(const float4*)(attn_l     + head * 64 + f4);
    float4 wr = *(const float4*)(attn_r     + head * 64 + f4);
    float4 wh = *(const float4*)(hop_attn_l + head * 64 + f4);
#pragma unroll
    for (int rr = 0; rr < 16; rr++) {
        int r = wid * 16 + rr;
        float4 v = *(const float4*)(smT + r * LDT + lane * 4);
        float pl = v.x * wl.x + v.y * wl.y + v.z * wl.z + v.w * wl.w;
        float pr = v.x * wr.x + v.y * wr.y + v.z * wr.z + v.w * wr.w;
        float ph = v.x * wh.x + v.y * wh.y + v.z * wh.z + v.w * wh.w;
#pragma unroll
        for (int o = 8; o; o >>= 1) {
            pl += __shfl_xor_sync(0xffffffffu, pl, o);
            pr += __shfl_xor_sync(0xffffffffu, pr, o);
            ph += __shfl_xor_sync(0xffffffffu, ph, o);
        }
        int node = row0 + r;
        if ((lane & 15) == 0 && node < NN) {
            g_el[node * 4 + head] = pl;
            g_er[node * 4 + head] = pr;
            g_al[node * 4 + head] = ph;
        }
    }
}

// fused edge pass: logits + exp + both segment sums + degrees
__global__ void edgeAB_kernel(const int* __restrict__ src, const int* __restrict__ dst) {
    int t = blockIdx.x * blockDim.x + threadIdx.x;
    if (t >= EH) return;
    int e = t >> 2, hd = t & 3;
    int s = src[e], d = dst[e];
    float ev = leaky(g_el[s * HH + hd] + g_er[d * HH + hd]);
    g_e[t] = ev;
    float ex = __expf(ev);
    atomicAdd(&g_sum_src[s * HH + hd], ex);
    atomicAdd(&g_sum_dst[d * HH + hd], ex);
    if (hd == 0) { atomicAdd(&g_outdeg[s], 1); atomicAdd(&g_indeg[d], 1); }
}

// degree norms + log of softmax denominators (in-place)
__global__ void norm_kernel() {
    int i = blockIdx.x * blockDim.x + threadIdx.x;
    if (i < NN) {
        g_nout[i] = rsqrtf((float)max(g_outdeg[i], 1));
        g_nin[i]  = sqrtf((float)max(g_indeg[i], 1));
    }
    if (i < NH) {
        g_sum_src[i] = __logf(g_sum_src[i]);
        g_sum_dst[i] = __logf(g_sum_dst[i]);
    }
}

// ---- two-level exclusive scan of indeg -> off ----
__global__ void scanA_kernel() {
    int t = threadIdx.x, lane = t & 31, wid = t >> 5;
    int idx = blockIdx.x * 256 + t;
    int v = (idx < NN) ? g_indeg[idx] : 0;
    int x = v;
#pragma unroll
    for (int o = 1; o < 32; o <<= 1) {
        int y = __shfl_up_sync(0xffffffffu, x, o);
        if (lane >= o) x += y;
    }
    __shared__ int ws[8];
    if (lane == 31) ws[wid] = x;
    __syncthreads();
    if (t < 8) {
        int y = ws[t];
#pragma unroll
        for (int o = 1; o < 8; o <<= 1) {
            int z = __shfl_up_sync(0xffu, y, o);
            if (t >= o) y += z;
        }
        ws[t] = y;
    }
    __syncthreads();
    int incl = x + (wid ? ws[wid - 1] : 0);
    if (idx < NN) g_off[idx] = incl - v;
    if (t == 255) g_bsum[blockIdx.x] = incl;
}

__global__ void scanB_kernel(int nblk) {
    int t = threadIdx.x, lane = t & 31, wid = t >> 5;
    int v = (t < nblk) ? g_bsum[t] : 0;
    int x = v;
#pragma unroll
    for (int o = 1; o < 32; o <<= 1) {
        int y = __shfl_up_sync(0xffffffffu, x, o);
        if (lane >= o) x += y;
    }
    __shared__ int ws[8];
    if (lane == 31) ws[wid] = x;
    __syncthreads();
    if (t < 8) {
        int y = ws[t];
#pragma unroll
        for (int o = 1; o < 8; o <<= 1) {
            int z = __shfl_up_sync(0xffu, y, o);
            if (t >= o) y += z;
        }
        ws[t] = y;
    }
    __syncthreads();
    int incl = x + (wid ? ws[wid - 1] : 0);
    g_boff[t] = incl - v;
}

__global__ void scanC_kernel() {
    int idx = blockIdx.x * 256 + threadIdx.x;
    if (idx < NN) g_off[idx] += g_boff[blockIdx.x];
    if (idx == 0) g_off[NN] = EE;
}

// fused scatter + coefficient: one thread per edge writes CSR slot + 4 head coeffs
__global__ void scatterC_kernel(const int* __restrict__ src, const int* __restrict__ dst,
                                const float* __restrict__ sigma) {
    int e = blockIdx.x * blockDim.x + threadIdx.x;
    if (e >= EE) return;
    int s = src[e], d = dst[e];
    int pos = g_off[d] + atomicAdd(&g_cnt[d], 1);
    g_csr_src[pos] = s;
    float sg = 1.f / (1.f + __expf(-sigma[0]));
    float no = g_nout[s];
    float4 ev = *(const float4*)(g_e + (size_t)e * 4);
    float4 ss = *(const float4*)(g_sum_src + (size_t)s * 4);
    float4 sd = *(const float4*)(g_sum_dst + (size_t)d * 4);
    float4 co;
    co.x = __expf((1.f - sg) * fmaxf(ev.x - ss.x, LCLIP) + sg * fmaxf(ev.x - sd.x, LCLIP)) * no;
    co.y = __expf((1.f - sg) * fmaxf(ev.y - ss.y, LCLIP) + sg * fmaxf(ev.y - sd.y, LCLIP)) * no;
    co.z = __expf((1.f - sg) * fmaxf(ev.z - ss.z, LCLIP) + sg * fmaxf(ev.z - sd.z, LCLIP)) * no;
    co.w = __expf((1.f - sg) * fmaxf(ev.w - ss.w, LCLIP) + sg * fmaxf(ev.w - sd.w, LCLIP)) * no;
    *(float4*)(g_c + (size_t)pos * 4) = co;
}

// shared gather body: accumulate Σ c*x[src] over in-edges of node n, head hd.
__device__ __forceinline__ void gather_row(const float* __restrict__ x, int n, int hd,
                                           int lane, float& ax, float& ay) {
    int beg = g_off[n], end = g_off[n + 1];
    int p = beg;
    for (; p + 7 < end; p += 8) {
        int s0 = g_csr_src[p],     s1 = g_csr_src[p + 1];
        int s2 = g_csr_src[p + 2], s3 = g_csr_src[p + 3];
        int s4 = g_csr_src[p + 4], s5 = g_csr_src[p + 5];
        int s6 = g_csr_src[p + 6], s7 = g_csr_src[p + 7];
        float c0 = g_c[p * 4 + hd],       c1 = g_c[(p + 1) * 4 + hd];
        float c2 = g_c[(p + 2) * 4 + hd], c3 = g_c[(p + 3) * 4 + hd];
        float c4 = g_c[(p + 4) * 4 + hd], c5 = g_c[(p + 5) * 4 + hd];
        float c6 = g_c[(p + 6) * 4 + hd], c7 = g_c[(p + 7) * 4 + hd];
        float2 v0 = ((const float2*)(x + (size_t)(s0 * 4 + hd) * FF))[lane];
        float2 v1 = ((const float2*)(x + (size_t)(s1 * 4 + hd) * FF))[lane];
        float2 v2 = ((const float2*)(x + (size_t)(s2 * 4 + hd) * FF))[lane];
        float2 v3 = ((const float2*)(x + (size_t)(s3 * 4 + hd) * FF))[lane];
        float2 v4 = ((const float2*)(x + (size_t)(s4 * 4 + hd) * FF))[lane];
        float2 v5 = ((const float2*)(x + (size_t)(s5 * 4 + hd) * FF))[lane];
        float2 v6 = ((const float2*)(x + (size_t)(s6 * 4 + hd) * FF))[lane];
        float2 v7 = ((const float2*)(x + (size_t)(s7 * 4 + hd) * FF))[lane];
        ax += c0 * v0.x + c1 * v1.x + c2 * v2.x + c3 * v3.x
            + c4 * v4.x + c5 * v5.x + c6 * v6.x + c7 * v7.x;
        ay += c0 * v0.y + c1 * v1.y + c2 * v2.y + c3 * v3.y
            + c4 * v4.y + c5 * v5.y + c6 * v6.y + c7 * v7.y;
    }
    for (; p + 1 < end; p += 2) {
        int s0 = g_csr_src[p], s1 = g_csr_src[p + 1];
        float c0 = g_c[p * 4 + hd], c1 = g_c[(p + 1) * 4 + hd];
        float2 v0 = ((const float2*)(x + (size_t)(s0 * 4 + hd) * FF))[lane];
        float2 v1 = ((const float2*)(x + (size_t)(s1 * 4 + hd) * FF))[lane];
        ax += c0 * v0.x + c1 * v1.x;
        ay += c0 * v0.y + c1 * v1.y;
    }
    if (p < end) {
        int s0 = g_csr_src[p];
        float c0 = g_c[p * 4 + hd];
        float2 v0 = ((const float2*)(x + (size_t)(s0 * 4 + hd) * FF))[lane];
        ax += c0 * v0.x;
        ay += c0 * v0.y;
    }
}

// hops 0 and 1: xn[d,h,:] = nin[d] * gather
__global__ void prop_kernel(int hop) {
    const float* x = (hop == 0) ? g_h : g_x1;
    float* xn      = (hop == 0) ? g_x1 : g_x2;
    int pair = blockIdx.x * 8 + (threadIdx.x >> 5);
    if (pair >= NH) return;
    int lane = threadIdx.x & 31;
    int n = pair >> 2, hd = pair & 3;
    float ax = 0.f, ay = 0.f;
    gather_row(x, n, hd, lane, ax, ay);
    float ni = g_nin[n];
    ((float2*)(xn + (size_t)pair * FF))[lane] = make_float2(ax * ni, ay * ni);
}

// final hop fused with hop-attention combine -> output (x3 never materialized)
__global__ void prop_combine_kernel(const float* __restrict__ hop_attn_r,
                                    float* __restrict__ out) {
    int pair = blockIdx.x * 8 + (threadIdx.x >> 5);
    if (pair >= NH) return;
    int lane = threadIdx.x & 31;
    int n = pair >> 2, hd = pair & 3;
    float ax = 0.f, ay = 0.f;
    gather_row(g_x2, n, hd, lane, ax, ay);
    float ni = g_nin[n];
    float2 v3 = make_float2(ax * ni, ay * ni);

    float2 wr = ((const float2*)(hop_attn_r + hd * FF))[lane];
    float2 v0 = ((const float2*)(g_h  + (size_t)pair * FF))[lane];
    float2 v1 = ((const float2*)(g_x1 + (size_t)pair * FF))[lane];
    float2 v2 = ((const float2*)(g_x2 + (size_t)pair * FF))[lane];
    float d0 = warpAllReduce(v0.x * wr.x + v0.y * wr.y);
    float d1 = warpAllReduce(v1.x * wr.x + v1.y * wr.y);
    float d2 = warpAllReduce(v2.x * wr.x + v2.y * wr.y);
    float d3 = warpAllReduce(v3.x * wr.x + v3.y * wr.y);
    float al = g_al[pair];
    float b0 = leaky(al + d0), b1 = leaky(al + d1);
    float b2 = leaky(al + d2), b3 = leaky(al + d3);
    float m = fmaxf(fmaxf(b0, b1), fmaxf(b2, b3));
    float e0 = __expf(b0 - m), e1 = __expf(b1 - m);
    float e2 = __expf(b2 - m), e3 = __expf(b3 - m);
    float inv = 1.f / (e0 + e1 + e2 + e3);
    e0 *= inv; e1 *= inv; e2 *= inv; e3 *= inv;
    float2 r;
    r.x = v0.x * e0 + v1.x * e1 + v2.x * e2 + v3.x * e3;
    r.y = v0.y * e0 + v1.y * e1 + v2.y * e2 + v3.y * e3;
    ((float2*)(out + (size_t)pair * FF))[lane] = r;
}

// ---------------- launch ----------------------------------------------------
extern "C" void kernel_launch(void* const* d_in, const int* in_sizes, int n_in,
                              void* d_out, int out_size) {
    const float* feat  = (const float*)d_in[0];
    const int*   src   = (const int*)d_in[1];
    const int*   dst   = (const int*)d_in[2];
    const float* W     = (const float*)d_in[3];
    const float* attn_l     = (const float*)d_in[4];
    const float* attn_r     = (const float*)d_in[5];
    const float* hop_attn_l = (const float*)d_in[6];
    const float* hop_attn_r = (const float*)d_in[7];
    const float* sigma      = (const float*)d_in[8];
    float* out = (float*)d_out;

    const int NBLK = (NN + 255) / 256;   // 196

    cudaFuncSetAttribute(gemm_wmma_kernel,
                         cudaFuncAttributeMaxDynamicSharedMemorySize, GS_BYTES);

    init_kernel<<<(NH + 255) / 256, 256>>>();
    convertW_kernel<<<64, 256>>>(W);
    gemm_wmma_kernel<<<dim3(NPAD / BM, 2), 256, GS_BYTES>>>(feat, attn_l, attn_r, hop_attn_l);
    edgeAB_kernel<<<(EH + 255) / 256, 256>>>(src, dst);
    norm_kernel<<<(NH + 255) / 256, 256>>>();
    scanA_kernel<<<NBLK, 256>>>();
    scanB_kernel<<<1, 256>>>(NBLK);
    scanC_kernel<<<NBLK, 256>>>();
    scatterC_kernel<<<(EE + 255) / 256, 256>>>(src, dst, sigma);
    prop_kernel<<<(NH + 7) / 8, 256>>>(0);
    prop_kernel<<<(NH + 7) / 8, 256>>>(1);
    prop_combine_kernel<<<(NH + 7) / 8, 256>>>(hop_attn_r, out);
}

// round 10
// speedup vs baseline: 1.4148x; 1.0484x over previous
#include <cuda_runtime.h>
#include <cuda_bf16.h>
#include <mma.h>
#include <math.h>
#include <stdint.h>

using namespace nvcuda;

#define NN 50000
#define NPAD 50048            // 391 * 128
#define EE 800000
#define INF_ 256
#define HH 4
#define FF 64
#define NH (NN*HH)            // 200000
#define EH (EE*HH)            // 3200000
#define SLOPE 0.2f
#define LCLIP (-23.0258509f)  // log(1e-10)

// ---------------- scratch (static device globals; no allocation) ------------
__device__ float g_h [NPAD*HH*FF];   // fp32 h (padded rows for wmma stores)
__device__ __nv_bfloat16 g_hb [NN*HH*FF];   // bf16 gather copies
__device__ __nv_bfloat16 g_x1b[NN*HH*FF];
__device__ __nv_bfloat16 g_x2b[NN*HH*FF];
__device__ float g_el[NH], g_er[NH], g_al[NH];
__device__ float g_sum_src[NH], g_sum_dst[NH];   // exp-sums, then logs in-place
__device__ float g_e[EH];      // leaky_relu(el[src]+er[dst])
__device__ float g_c[EE*HH];   // per-edge coefficient, CSR order: [pos][hd]
__device__ int   g_indeg[NN], g_outdeg[NN], g_cnt[NN];
__device__ int   g_off[NN+1];
__device__ int   g_csr_src[EE];
__device__ float g_nin[NN], g_nout[NN];
__device__ int   g_bsum[256], g_boff[256];
__device__ __nv_bfloat16 g_Wh[256*256];   // [k][n] row-major, split hi/lo
__device__ __nv_bfloat16 g_Wl[256*256];

// ---------------- helpers ---------------------------------------------------
__device__ __forceinline__ float leaky(float x) { return x > 0.f ? x : SLOPE * x; }

__device__ __forceinline__ float warpAllReduce(float v) {
#pragma unroll
    for (int o = 16; o; o >>= 1) v += __shfl_xor_sync(0xffffffffu, v, o);
    return v;
}

// ---------------- kernels ---------------------------------------------------
__global__ void init_kernel() {
    int i = blockIdx.x * blockDim.x + threadIdx.x;
    if (i < NN) { g_indeg[i] = 0; g_outdeg[i] = 0; g_cnt[i] = 0; }
    if (i < NH) { g_sum_src[i] = 0.f; g_sum_dst[i] = 0.f; }
}

// W -> split bf16 hi/lo, same [k][n] layout
__global__ void convertW_kernel(const float* __restrict__ W) {
    int idx = blockIdx.x * 256 + threadIdx.x;      // 65536/4 threads
    if (idx >= 64 * 256) return;
    float4 v = ((const float4*)W)[idx];
    __nv_bfloat16 hx = __float2bfloat16_rn(v.x), hy = __float2bfloat16_rn(v.y);
    __nv_bfloat16 hz = __float2bfloat16_rn(v.z), hw = __float2bfloat16_rn(v.w);
    ((__nv_bfloat162*)g_Wh)[idx * 2]     = __nv_bfloat162(hx, hy);
    ((__nv_bfloat162*)g_Wh)[idx * 2 + 1] = __nv_bfloat162(hz, hw);
    ((__nv_bfloat162*)g_Wl)[idx * 2]     = __nv_bfloat162(
        __float2bfloat16_rn(v.x - __bfloat162float(hx)),
        __float2bfloat16_rn(v.y - __bfloat162float(hy)));
    ((__nv_bfloat162*)g_Wl)[idx * 2 + 1] = __nv_bfloat162(
        __float2bfloat16_rn(v.z - __bfloat162float(hz)),
        __float2bfloat16_rn(v.w - __bfloat162float(hw)));
}

// tensor-core GEMM via wmma, split-bf16 3-product emulation, inline A convert,
// double-buffered smem, fused el/er/al dots + bf16 h-copy epilogue.
#define BM 128
#define BN 128
#define BK 64
#define LDA 72     // 64 + 8 pad (bf16)
#define LDB 136    // 128 + 8 pad
#define CH_AH 0
#define CH_AL (BM*LDA)
#define CH_BH (2*BM*LDA)
#define CH_BL (2*BM*LDA + BK*LDB)
#define CH_ELEM (2*BM*LDA + 2*BK*LDB)            // 35840 bf16 per buffer
#define GS_BYTES (2*CH_ELEM*2)                   // 143360 B
#define LDT 132                                  // fp32 tile ld for epilogue

struct Pref {
    float4 a[8];
    uint4  bh[4], bl[4];
};

__device__ __forceinline__ void gemm_load(Pref& P, const float* __restrict__ feat,
                                          int row0, int col0, int c, int tid) {
#pragma unroll
    for (int u = 0; u < 8; u++) {
        int idx = tid + u * 256;                  // 0..2047
        int r = idx >> 4, kq = idx & 15;
        int row = row0 + r;
        P.a[u] = (row < NN)
            ? *(const float4*)(feat + (size_t)row * 256 + c * 64 + kq * 4)
            : make_float4(0.f, 0.f, 0.f, 0.f);
    }
#pragma unroll
    for (int u = 0; u < 4; u++) {
        int idx = tid + u * 256;                  // 0..1023
        int r = idx >> 4, cq = idx & 15;
        size_t g = (size_t)(c * 64 + r) * 256 + col0 + cq * 8;
        P.bh[u] = *(const uint4*)(g_Wh + g);
        P.bl[u] = *(const uint4*)(g_Wl + g);
    }
}

__device__ __forceinline__ void gemm_store(const Pref& P, __nv_bfloat16* buf, int tid) {
#pragma unroll
    for (int u = 0; u < 8; u++) {
        int idx = tid + u * 256;
        int r = idx >> 4, kq = idx & 15;
        float4 v = P.a[u];
        __nv_bfloat16 hx = __float2bfloat16_rn(v.x), hy = __float2bfloat16_rn(v.y);
        __nv_bfloat16 hz = __float2bfloat16_rn(v.z), hw = __float2bfloat16_rn(v.w);
        __nv_bfloat16* ph = buf + CH_AH + r * LDA + kq * 4;
        __nv_bfloat16* pl = buf + CH_AL + r * LDA + kq * 4;
        *(__nv_bfloat162*)ph       = __nv_bfloat162(hx, hy);
        *(__nv_bfloat162*)(ph + 2) = __nv_bfloat162(hz, hw);
        *(__nv_bfloat162*)pl       = __nv_bfloat162(
            __float2bfloat16_rn(v.x - __bfloat162float(hx)),
            __float2bfloat16_rn(v.y - __bfloat162float(hy)));
        *(__nv_bfloat162*)(pl + 2) = __nv_bfloat162(
            __float2bfloat16_rn(v.z - __bfloat162float(hz)),
            __float2bfloat16_rn(v.w - __bfloat162float(hw)));
    }
#pragma unroll
    for (int u = 0; u < 4; u++) {
        int idx = tid + u * 256;
        int r = idx >> 4, cq = idx & 15;
        *(uint4*)(buf + CH_BH + r * LDB + cq * 8) = P.bh[u];
        *(uint4*)(buf + CH_BL + r * LDB + cq * 8) = P.bl[u];
    }
}

__global__ void __launch_bounds__(256) gemm_wmma_kernel(const float* __restrict__ feat,
                                                        const float* __restrict__ attn_l,
                                                        const float* __restrict__ attn_r,
                                                        const float* __restrict__ hop_attn_l) {
    extern __shared__ __nv_bfloat16 sm[];
    __nv_bfloat16* buf0 = sm;
    __nv_bfloat16* buf1 = sm + CH_ELEM;
    int tid = threadIdx.x, wid = tid >> 5, lane = tid & 31;
    int wy = wid & 3, wx = wid >> 2;              // 4 x 2 warp grid
    int row0 = blockIdx.x * BM, col0 = blockIdx.y * BN;

    wmma::fragment<wmma::accumulator, 16, 16, 16, float> acc[2][4];
#pragma unroll
    for (int i = 0; i < 2; i++)
#pragma unroll
        for (int j = 0; j < 4; j++) wmma::fill_fragment(acc[i][j], 0.f);

    Pref P;
    gemm_load(P, feat, row0, col0, 0, tid);
    gemm_store(P, buf0, tid);
    __syncthreads();

    for (int c = 0; c < 4; c++) {
        __nv_bfloat16* cur = (c & 1) ? buf1 : buf0;
        __nv_bfloat16* nxt = (c & 1) ? buf0 : buf1;
        if (c < 3) gemm_load(P, feat, row0, col0, c + 1, tid);   // LDG overlaps MMA

#pragma unroll
        for (int kk = 0; kk < 4; kk++) {
            wmma::fragment<wmma::matrix_a, 16, 16, 16, __nv_bfloat16, wmma::row_major> fa_h[2], fa_l[2];
            wmma::fragment<wmma::matrix_b, 16, 16, 16, __nv_bfloat16, wmma::row_major> fb_h[4], fb_l[4];
#pragma unroll
            for (int i = 0; i < 2; i++) {
                const __nv_bfloat16* p = cur + CH_AH + (wy * 32 + i * 16) * LDA + kk * 16;
                wmma::load_matrix_sync(fa_h[i], p, LDA);
                wmma::load_matrix_sync(fa_l[i], p + (CH_AL - CH_AH), LDA);
            }
#pragma unroll
            for (int j = 0; j < 4; j++) {
                const __nv_bfloat16* p = cur + CH_BH + (kk * 16) * LDB + wx * 64 + j * 16;
                wmma::load_matrix_sync(fb_h[j], p, LDB);
                wmma::load_matrix_sync(fb_l[j], p + (CH_BL - CH_BH), LDB);
            }
#pragma unroll
            for (int i = 0; i < 2; i++)
#pragma unroll
                for (int j = 0; j < 4; j++) {
                    wmma::mma_sync(acc[i][j], fa_h[i], fb_h[j], acc[i][j]);
                    wmma::mma_sync(acc[i][j], fa_h[i], fb_l[j], acc[i][j]);
                    wmma::mma_sync(acc[i][j], fa_l[i], fb_h[j], acc[i][j]);
                }
        }
        if (c < 3) gemm_store(P, nxt, tid);
        __syncthreads();
    }
    // store 32x64 per warp (g_h row-padded to NPAD, no guards) + smem for dots
    float* smT = (float*)sm;                     // 128 x LDT fp32 tile
#pragma unroll
    for (int i = 0; i < 2; i++)
#pragma unroll
        for (int j = 0; j < 4; j++) {
            float* pg = g_h + (size_t)(row0 + wy * 32 + i * 16) * 256 + col0 + wx * 64 + j * 16;
            wmma::store_matrix_sync(pg, acc[i][j], 256, wmma::mem_row_major);
            wmma::store_matrix_sync(smT + (wy * 32 + i * 16) * LDT + wx * 64 + j * 16,
                                    acc[i][j], LDT, wmma::mem_row_major);
        }
    __syncthreads();

    // fused epilogue: dots for heads {2*by, 2*by+1} + bf16 h-copy for gathers.
    int hsel = lane >> 4;
    int head = blockIdx.y * 2 + hsel;
    int f4 = (lane & 15) * 4;
    float4 wl = *(const float4*)(attn_l     + head * 64 + f4);
    float4 wr = *(const float4*)(attn_r     + head * 64 + f4);
    float4 wh = *(const float4*)(hop_attn_l + head * 64 + f4);
#pragma unroll
    for (int rr = 0; rr < 16; rr++) {
        int r = wid * 16 + rr;
        int node = row0 + r;
        float4 v = *(const float4*)(smT + r * LDT + lane * 4);
        if (node < NN) {
            __nv_bfloat16* pb = g_hb + (size_t)node * 256 + col0 + lane * 4;
            *(__nv_bfloat162*)pb       = __nv_bfloat162(__float2bfloat16_rn(v.x),
                                                        __float2bfloat16_rn(v.y));
            *(__nv_bfloat162*)(pb + 2) = __nv_bfloat162(__float2bfloat16_rn(v.z),
                                                        __float2bfloat16_rn(v.w));
        }
        float pl = v.x * wl.x + v.y * wl.y + v.z * wl.z + v.w * wl.w;
        float pr = v.x * wr.x + v.y * wr.y + v.z * wr.z + v.w * wr.w;
        float ph = v.x * wh.x + v.y * wh.y + v.z * wh.z + v.w * wh.w;
#pragma unroll
        for (int o = 8; o; o >>= 1) {
            pl += __shfl_xor_sync(0xffffffffu, pl, o);
            pr += __shfl_xor_sync(0xffffffffu, pr, o);
            ph += __shfl_xor_sync(0xffffffffu, ph, o);
        }
        if ((lane & 15) == 0 && node < NN) {
            g_el[node * 4 + head] = pl;
            g_er[node * 4 + head] = pr;
            g_al[node * 4 + head] = ph;
        }
    }
}

// fused edge pass: logits + exp + both segment sums + degrees
__global__ void edgeAB_kernel(const int* __restrict__ src, const int* __restrict__ dst) {
    int t = blockIdx.x * blockDim.x + threadIdx.x;
    if (t >= EH) return;
    int e = t >> 2, hd = t & 3;
    int s = src[e], d = dst[e];
    float ev = leaky(g_el[s * HH + hd] + g_er[d * HH + hd]);
    g_e[t] = ev;
    float ex = __expf(ev);
    atomicAdd(&g_sum_src[s * HH + hd], ex);
    atomicAdd(&g_sum_dst[d * HH + hd], ex);
    if (hd == 0) { atomicAdd(&g_outdeg[s], 1); atomicAdd(&g_indeg[d], 1); }
}

// ---- scanA: fused degree norms + log-denominators + block scan of indeg ----
__global__ void scanA_kernel() {
    int t = threadIdx.x, lane = t & 31, wid = t >> 5;
    int idx = blockIdx.x * 256 + t;
    int v = (idx < NN) ? g_indeg[idx] : 0;
    if (idx < NN) {
        g_nout[idx] = rsqrtf((float)max(g_outdeg[idx], 1));
        g_nin[idx]  = sqrtf((float)max(v, 1));
        float4 ss = *(float4*)(g_sum_src + (size_t)idx * 4);
        float4 sd = *(float4*)(g_sum_dst + (size_t)idx * 4);
        ss.x = __logf(ss.x); ss.y = __logf(ss.y); ss.z = __logf(ss.z); ss.w = __logf(ss.w);
        sd.x = __logf(sd.x); sd.y = __logf(sd.y); sd.z = __logf(sd.z); sd.w = __logf(sd.w);
        *(float4*)(g_sum_src + (size_t)idx * 4) = ss;
        *(float4*)(g_sum_dst + (size_t)idx * 4) = sd;
    }
    int x = v;
#pragma unroll
    for (int o = 1; o < 32; o <<= 1) {
        int y = __shfl_up_sync(0xffffffffu, x, o);
        if (lane >= o) x += y;
    }
    __shared__ int ws[8];
    if (lane == 31) ws[wid] = x;
    __syncthreads();
    if (t < 8) {
        int y = ws[t];
#pragma unroll
        for (int o = 1; o < 8; o <<= 1) {
            int z = __shfl_up_sync(0xffu, y, o);
            if (t >= o) y += z;
        }
        ws[t] = y;
    }
    __syncthreads();
    int incl = x + (wid ? ws[wid - 1] : 0);
    if (idx < NN) g_off[idx] = incl - v;
    if (t == 255) g_bsum[blockIdx.x] = incl;
}

__global__ void scanB_kernel(int nblk) {
    int t = threadIdx.x, lane = t & 31, wid = t >> 5;
    int v = (t < nblk) ? g_bsum[t] : 0;
    int x = v;
#pragma unroll
    for (int o = 1; o < 32; o <<= 1) {
        int y = __shfl_up_sync(0xffffffffu, x, o);
        if (lane >= o) x += y;
    }
    __shared__ int ws[8];
    if (lane == 31) ws[wid] = x;
    __syncthreads();
    if (t < 8) {
        int y = ws[t];
#pragma unroll
        for (int o = 1; o < 8; o <<= 1) {
            int z = __shfl_up_sync(0xffu, y, o);
            if (t >= o) y += z;
        }
        ws[t] = y;
    }
    __syncthreads();
    int incl = x + (wid ? ws[wid - 1] : 0);
    g_boff[t] = incl - v;
}

__global__ void scanC_kernel() {
    int idx = blockIdx.x * 256 + threadIdx.x;
    if (idx < NN) g_off[idx] += g_boff[blockIdx.x];
    if (idx == 0) g_off[NN] = EE;
}

// fused scatter + coefficient: one thread per edge writes CSR slot + 4 head coeffs
__global__ void scatterC_kernel(const int* __restrict__ src, const int* __restrict__ dst,
                                const float* __restrict__ sigma) {
    int e = blockIdx.x * blockDim.x + threadIdx.x;
    if (e >= EE) return;
    int s = src[e], d = dst[e];
    int pos = g_off[d] + atomicAdd(&g_cnt[d], 1);
    g_csr_src[pos] = s;
    float sg = 1.f / (1.f + __expf(-sigma[0]));
    float no = g_nout[s];
    float4 ev = *(const float4*)(g_e + (size_t)e * 4);
    float4 ss = *(const float4*)(g_sum_src + (size_t)s * 4);
    float4 sd = *(const float4*)(g_sum_dst + (size_t)d * 4);
    float4 co;
    co.x = __expf((1.f - sg) * fmaxf(ev.x - ss.x, LCLIP) + sg * fmaxf(ev.x - sd.x, LCLIP)) * no;
    co.y = __expf((1.f - sg) * fmaxf(ev.y - ss.y, LCLIP) + sg * fmaxf(ev.y - sd.y, LCLIP)) * no;
    co.z = __expf((1.f - sg) * fmaxf(ev.z - ss.z, LCLIP) + sg * fmaxf(ev.z - sd.z, LCLIP)) * no;
    co.w = __expf((1.f - sg) * fmaxf(ev.w - ss.w, LCLIP) + sg * fmaxf(ev.w - sd.w, LCLIP)) * no;
    *(float4*)(g_c + (size_t)pos * 4) = co;
}

// shared gather body over bf16 rows: Σ c*x[src] for node n, head hd.
// lane covers cols 2*lane, 2*lane+1 (bfloat162 = 4 B/lane, 128 B/warp/edge).
__device__ __forceinline__ void gather_row_bf(const __nv_bfloat16* __restrict__ xb,
                                              int n, int hd, int lane,
                                              float& ax, float& ay) {
    int beg = g_off[n], end = g_off[n + 1];
    int p = beg;
    for (; p + 7 < end; p += 8) {
        int s0 = g_csr_src[p],     s1 = g_csr_src[p + 1];
        int s2 = g_csr_src[p + 2], s3 = g_csr_src[p + 3];
        int s4 = g_csr_src[p + 4], s5 = g_csr_src[p + 5];
        int s6 = g_csr_src[p + 6], s7 = g_csr_src[p + 7];
        float c0 = g_c[p * 4 + hd],       c1 = g_c[(p + 1) * 4 + hd];
        float c2 = g_c[(p + 2) * 4 + hd], c3 = g_c[(p + 3) * 4 + hd];
        float c4 = g_c[(p + 4) * 4 + hd], c5 = g_c[(p + 5) * 4 + hd];
        float c6 = g_c[(p + 6) * 4 + hd], c7 = g_c[(p + 7) * 4 + hd];
        float2 v0 = __bfloat1622float2(((const __nv_bfloat162*)(xb + (size_t)(s0 * 4 + hd) * FF))[lane]);
        float2 v1 = __bfloat1622float2(((const __nv_bfloat162*)(xb + (size_t)(s1 * 4 + hd) * FF))[lane]);
        float2 v2 = __bfloat1622float2(((const __nv_bfloat162*)(xb + (size_t)(s2 * 4 + hd) * FF))[lane]);
        float2 v3 = __bfloat1622float2(((const __nv_bfloat162*)(xb + (size_t)(s3 * 4 + hd) * FF))[lane]);
        float2 v4 = __bfloat1622float2(((const __nv_bfloat162*)(xb + (size_t)(s4 * 4 + hd) * FF))[lane]);
        float2 v5 = __bfloat1622float2(((const __nv_bfloat162*)(xb + (size_t)(s5 * 4 + hd) * FF))[lane]);
        float2 v6 = __bfloat1622float2(((const __nv_bfloat162*)(xb + (size_t)(s6 * 4 + hd) * FF))[lane]);
        float2 v7 = __bfloat1622float2(((const __nv_bfloat162*)(xb + (size_t)(s7 * 4 + hd) * FF))[lane]);
        ax += c0 * v0.x + c1 * v1.x + c2 * v2.x + c3 * v3.x
            + c4 * v4.x + c5 * v5.x + c6 * v6.x + c7 * v7.x;
        ay += c0 * v0.y + c1 * v1.y + c2 * v2.y + c3 * v3.y
            + c4 * v4.y + c5 * v5.y + c6 * v6.y + c7 * v7.y;
    }
    for (; p + 1 < end; p += 2) {
        int s0 = g_csr_src[p], s1 = g_csr_src[p + 1];
        float c0 = g_c[p * 4 + hd], c1 = g_c[(p + 1) * 4 + hd];
        float2 v0 = __bfloat1622float2(((const __nv_bfloat162*)(xb + (size_t)(s0 * 4 + hd) * FF))[lane]);
        float2 v1 = __bfloat1622float2(((const __nv_bfloat162*)(xb + (size_t)(s1 * 4 + hd) * FF))[lane]);
        ax += c0 * v0.x + c1 * v1.x;
        ay += c0 * v0.y + c1 * v1.y;
    }
    if (p < end) {
        int s0 = g_csr_src[p];
        float c0 = g_c[p * 4 + hd];
        float2 v0 = __bfloat1622float2(((const __nv_bfloat162*)(xb + (size_t)(s0 * 4 + hd) * FF))[lane]);
        ax += c0 * v0.x;
        ay += c0 * v0.y;
    }
}

// hops 0 and 1: xn[d,h,:] = nin[d] * gather (bf16 in, bf16 out)
__global__ void prop_kernel(int hop) {
    const __nv_bfloat16* xb = (hop == 0) ? g_hb : g_x1b;
    __nv_bfloat16* xnb      = (hop == 0) ? g_x1b : g_x2b;
    int pair = blockIdx.x * 8 + (threadIdx.x >> 5);
    if (pair >= NH) return;
    int lane = threadIdx.x & 31;
    int n = pair >> 2, hd = pair & 3;
    float ax = 0.f, ay = 0.f;
    gather_row_bf(xb, n, hd, lane, ax, ay);
    float ni = g_nin[n];
    ((__nv_bfloat162*)(xnb + (size_t)pair * FF))[lane] =
        __nv_bfloat162(__float2bfloat16_rn(ax * ni), __float2bfloat16_rn(ay * ni));
}

// final hop fused with hop-attention combine -> output (x3 never materialized)
__global__ void prop_combine_kernel(const float* __restrict__ hop_attn_r,
                                    float* __restrict__ out) {
    int pair = blockIdx.x * 8 + (threadIdx.x >> 5);
    if (pair >= NH) return;
    int lane = threadIdx.x & 31;
    int n = pair >> 2, hd = pair & 3;
    float ax = 0.f, ay = 0.f;
    gather_row_bf(g_x2b, n, hd, lane, ax, ay);
    float ni = g_nin[n];
    float2 v3 = make_float2(ax * ni, ay * ni);

    float2 wr = ((const float2*)(hop_attn_r + hd * FF))[lane];
    float2 v0 = ((const float2*)(g_h + (size_t)pair * FF))[lane];
    float2 v1 = __bfloat1622float2(((const __nv_bfloat162*)(g_x1b + (size_t)pair * FF))[lane]);
    float2 v2 = __bfloat1622float2(((const __nv_bfloat162*)(g_x2b + (size_t)pair * FF))[lane]);
    float d0 = warpAllReduce(v0.x * wr.x + v0.y * wr.y);
    float d1 = warpAllReduce(v1.x * wr.x + v1.y * wr.y);
    float d2 = warpAllReduce(v2.x * wr.x + v2.y * wr.y);
    float d3 = warpAllReduce(v3.x * wr.x + v3.y * wr.y);
    float al = g_al[pair];
    float b0 = leaky(al + d0), b1 = leaky(al + d1);
    float b2 = leaky(al + d2), b3 = leaky(al + d3);
    float m = fmaxf(fmaxf(b0, b1), fmaxf(b2, b3));
    float e0 = __expf(b0 - m), e1 = __expf(b1 - m);
    float e2 = __expf(b2 - m), e3 = __expf(b3 - m);
    float inv = 1.f / (e0 + e1 + e2 + e3);
    e0 *= inv; e1 *= inv; e2 *= inv; e3 *= inv;
    float2 r;
    r.x = v0.x * e0 + v1.x * e1 + v2.x * e2 + v3.x * e3;
    r.y = v0.y * e0 + v1.y * e1 + v2.y * e2 + v3.y * e3;
    ((float2*)(out + (size_t)pair * FF))[lane] = r;
}

// ---------------- launch ----------------------------------------------------
extern "C" void kernel_launch(void* const* d_in, const int* in_sizes, int n_in,
                              void* d_out, int out_size) {
    const float* feat  = (const float*)d_in[0];
    const int*   src   = (const int*)d_in[1];
    const int*   dst   = (const int*)d_in[2];
    const float* W     = (const float*)d_in[3];
    const float* attn_l     = (const float*)d_in[4];
    const float* attn_r     = (const float*)d_in[5];
    const float* hop_attn_l = (const float*)d_in[6];
    const float* hop_attn_r = (const float*)d_in[7];
    const float* sigma      = (const float*)d_in[8];
    float* out = (float*)d_out;

    const int NBLK = (NN + 255) / 256;   // 196

    cudaFuncSetAttribute(gemm_wmma_kernel,
                         cudaFuncAttributeMaxDynamicSharedMemorySize, GS_BYTES);

    init_kernel<<<(NH + 255) / 256, 256>>>();
    convertW_kernel<<<64, 256>>>(W);
    gemm_wmma_kernel<<<dim3(NPAD / BM, 2), 256, GS_BYTES>>>(feat, attn_l, attn_r, hop_attn_l);
    edgeAB_kernel<<<(EH + 255) / 256, 256>>>(src, dst);
    scanA_kernel<<<NBLK, 256>>>();
    scanB_kernel<<<1, 256>>>(NBLK);
    scanC_kernel<<<NBLK, 256>>>();
    scatterC_kernel<<<(EE + 255) / 256, 256>>>(src, dst, sigma);
    prop_kernel<<<(NH + 7) / 8, 256>>>(0);
    prop_kernel<<<(NH + 7) / 8, 256>>>(1);
    prop_combine_kernel<<<(NH + 7) / 8, 256>>>(hop_attn_r, out);
}